// round 16
// baseline (speedup 1.0000x reference)
#include <cuda_runtime.h>
#include <math.h>
#include <stdint.h>

static constexpr int kB  = 2;
static constexpr int kNX = 512;
static constexpr int kNC = 4096;
static constexpr int kD  = 1024;
static constexpr int kH  = 16;
static constexpr int kHD = 64;
#define ATT_SCALE 0.125f   // HD^-0.5

static constexpr int kNT     = kNX / 64 + kNC / 64;  // 72 key tiles
static constexpr int kSplits = 2;
static constexpr int kNTS    = kNT / kSplits;        // 36 tiles per split
static constexpr int kPO_N   = kB * kNX * kD;        // floats per split partial
static constexpr int kML_N   = kB * kNX * kH;        // float2 per split

// Scratch (allocation-free rule: __device__ globals)
__device__ float g_xn[kB * kNX * kD];
__device__ float g_q [kB * kNX * kD];
__device__ float g_a [kB * kNX * kD];
__device__ float g_cr[kB * kNC * kD];                // RNA-rounded ctx
__device__ float g_pO[kSplits * kPO_N];              // split partial O
__device__ float2 g_ml[kSplits * kML_N];             // split (m, l)
__device__ uint32_t g_mbits[(size_t)kB * kNX * kNC / 32];

// ---------------------------------------------------------------------------
// tf32 mma helpers
// ---------------------------------------------------------------------------
__device__ __forceinline__ uint32_t cvt_tf32(float x) {
    uint32_t u;
    asm("cvt.rna.tf32.f32 %0, %1;" : "=r"(u) : "f"(x));
    return u;
}
__device__ __forceinline__ void mma_tf32(float c[4], const uint32_t a[4],
                                         uint32_t b0, uint32_t b1) {
    asm volatile(
        "mma.sync.aligned.m16n8k8.row.col.f32.tf32.tf32.f32 "
        "{%0,%1,%2,%3}, {%4,%5,%6,%7}, {%8,%9}, {%0,%1,%2,%3};"
        : "+f"(c[0]), "+f"(c[1]), "+f"(c[2]), "+f"(c[3])
        : "r"(a[0]), "r"(a[1]), "r"(a[2]), "r"(a[3]), "r"(b0), "r"(b1));
}

// ---------------------------------------------------------------------------
// cp.async helpers
// ---------------------------------------------------------------------------
__device__ __forceinline__ void cpa16(uint32_t dst, const void* src) {
    asm volatile("cp.async.cg.shared.global [%0], [%1], 16;"
                 :: "r"(dst), "l"(src));
}
__device__ __forceinline__ void cp_commit() {
    asm volatile("cp.async.commit_group;" ::: "memory");
}
__device__ __forceinline__ void cp_wait1() {
    asm volatile("cp.async.wait_group 1;" ::: "memory");
}
__device__ __forceinline__ void cp_wait0() {
    asm volatile("cp.async.wait_group 0;" ::: "memory");
}

// ---------------------------------------------------------------------------
// LayerNorm
// ---------------------------------------------------------------------------
__global__ __launch_bounds__(256) void ln_kernel(
    const float* __restrict__ x, const float* __restrict__ w,
    const float* __restrict__ bb, float* __restrict__ out)
{
    int row = blockIdx.x;
    int tid = threadIdx.x;
    float4 v = reinterpret_cast<const float4*>(x + (size_t)row * kD)[tid];
    float s  = v.x + v.y + v.z + v.w;
    float sq = v.x*v.x + v.y*v.y + v.z*v.z + v.w*v.w;
    #pragma unroll
    for (int o = 16; o; o >>= 1) {
        s  += __shfl_xor_sync(0xffffffffu, s,  o);
        sq += __shfl_xor_sync(0xffffffffu, sq, o);
    }
    __shared__ float ss[8], ssq[8];
    int wid = tid >> 5, lid = tid & 31;
    if (lid == 0) { ss[wid] = s; ssq[wid] = sq; }
    __syncthreads();
    if (wid == 0) {
        s  = (lid < 8) ? ss[lid]  : 0.f;
        sq = (lid < 8) ? ssq[lid] : 0.f;
        #pragma unroll
        for (int o = 4; o; o >>= 1) {
            s  += __shfl_xor_sync(0xffffffffu, s,  o);
            sq += __shfl_xor_sync(0xffffffffu, sq, o);
        }
        if (lid == 0) { ss[0] = s; ssq[0] = sq; }
    }
    __syncthreads();
    float mu   = ss[0] * (1.f / kD);
    float var  = ssq[0] * (1.f / kD) - mu * mu;
    float rstd = rsqrtf(var + 1e-5f);
    float4 w4 = reinterpret_cast<const float4*>(w)[tid];
    float4 b4 = reinterpret_cast<const float4*>(bb)[tid];
    float4 o4;
    o4.x = (v.x - mu) * rstd * w4.x + b4.x;
    o4.y = (v.y - mu) * rstd * w4.y + b4.y;
    o4.z = (v.z - mu) * rstd * w4.z + b4.z;
    o4.w = (v.w - mu) * rstd * w4.w + b4.w;
    reinterpret_cast<float4*>(out + (size_t)row * kD)[tid] = o4;
}

// ---------------------------------------------------------------------------
// 3xTF32 split GEMM: C = A @ B, fp32-accurate. rnd!=0 -> RNA-round outputs.
// ---------------------------------------------------------------------------
static constexpr int TG_AH = 0;
static constexpr int TG_AL = 4608;
static constexpr int TG_BH = 9216;
static constexpr int TG_BL = 11520;
static constexpr int TG_TOT = 13824;
static constexpr int TG_SMEM_BYTES = TG_TOT * 4;

__global__ __launch_bounds__(256) void tgemm_kernel(
    const float* __restrict__ A, const float* __restrict__ Bm,
    float* __restrict__ C, int M, int N, int K, int rnd)
{
    extern __shared__ float ts[];
    float* Ah = ts + TG_AH;
    float* Al = ts + TG_AL;
    float* Bh = ts + TG_BH;
    float* Bl = ts + TG_BL;

    int tid  = threadIdx.x;
    int lane = tid & 31, wid = tid >> 5;
    int gr = lane >> 2, qq = lane & 3;
    int wm = wid >> 1, wn = wid & 1;
    int m0 = blockIdx.y * 128, n0 = blockIdx.x * 64;

    float acc[2][4][4];
    #pragma unroll
    for (int mi = 0; mi < 2; mi++)
        #pragma unroll
        for (int ni = 0; ni < 4; ni++)
            #pragma unroll
            for (int e = 0; e < 4; e++) acc[mi][ni][e] = 0.f;

    for (int k0 = 0; k0 < K; k0 += 32) {
        __syncthreads();
        #pragma unroll
        for (int j = 0; j < 4; j++) {
            int f = tid + 256 * j;
            int m = f >> 3, c4 = f & 7;
            float4 v = *reinterpret_cast<const float4*>(
                A + (size_t)(m0 + m) * K + k0 + c4 * 4);
            uint4 hb, lb;
            hb.x = cvt_tf32(v.x); lb.x = cvt_tf32(v.x - __uint_as_float(hb.x));
            hb.y = cvt_tf32(v.y); lb.y = cvt_tf32(v.y - __uint_as_float(hb.y));
            hb.z = cvt_tf32(v.z); lb.z = cvt_tf32(v.z - __uint_as_float(hb.z));
            hb.w = cvt_tf32(v.w); lb.w = cvt_tf32(v.w - __uint_as_float(hb.w));
            *reinterpret_cast<uint4*>(&Ah[m * 36 + c4 * 4]) = hb;
            *reinterpret_cast<uint4*>(&Al[m * 36 + c4 * 4]) = lb;
        }
        #pragma unroll
        for (int j = 0; j < 2; j++) {
            int f = tid + 256 * j;
            int kk = f >> 4, c4 = f & 15;
            float4 v = *reinterpret_cast<const float4*>(
                Bm + (size_t)(k0 + kk) * N + n0 + c4 * 4);
            uint4 hb, lb;
            hb.x = cvt_tf32(v.x); lb.x = cvt_tf32(v.x - __uint_as_float(hb.x));
            hb.y = cvt_tf32(v.y); lb.y = cvt_tf32(v.y - __uint_as_float(hb.y));
            hb.z = cvt_tf32(v.z); lb.z = cvt_tf32(v.z - __uint_as_float(hb.z));
            hb.w = cvt_tf32(v.w); lb.w = cvt_tf32(v.w - __uint_as_float(hb.w));
            *reinterpret_cast<uint4*>(&Bh[kk * 72 + c4 * 4]) = hb;
            *reinterpret_cast<uint4*>(&Bl[kk * 72 + c4 * 4]) = lb;
        }
        __syncthreads();

        #pragma unroll
        for (int ks = 0; ks < 4; ks++) {
            int ko = ks * 8 + qq;
            uint32_t ah[2][4], al[2][4];
            #pragma unroll
            for (int mi = 0; mi < 2; mi++) {
                int row = (wm * 32 + mi * 16 + gr) * 36;
                ah[mi][0] = __float_as_uint(Ah[row + ko]);
                ah[mi][1] = __float_as_uint(Ah[row + 8 * 36 + ko]);
                ah[mi][2] = __float_as_uint(Ah[row + ko + 4]);
                ah[mi][3] = __float_as_uint(Ah[row + 8 * 36 + ko + 4]);
                al[mi][0] = __float_as_uint(Al[row + ko]);
                al[mi][1] = __float_as_uint(Al[row + 8 * 36 + ko]);
                al[mi][2] = __float_as_uint(Al[row + ko + 4]);
                al[mi][3] = __float_as_uint(Al[row + 8 * 36 + ko + 4]);
            }
            #pragma unroll
            for (int ni = 0; ni < 4; ni++) {
                int n = wn * 32 + ni * 8 + gr;
                uint32_t bh0 = __float_as_uint(Bh[ko * 72 + n]);
                uint32_t bh1 = __float_as_uint(Bh[(ko + 4) * 72 + n]);
                uint32_t bl0 = __float_as_uint(Bl[ko * 72 + n]);
                uint32_t bl1 = __float_as_uint(Bl[(ko + 4) * 72 + n]);
                #pragma unroll
                for (int mi = 0; mi < 2; mi++) {
                    mma_tf32(acc[mi][ni], ah[mi], bh0, bh1);
                    mma_tf32(acc[mi][ni], ah[mi], bl0, bl1);
                    mma_tf32(acc[mi][ni], al[mi], bh0, bh1);
                }
            }
        }
    }
    #pragma unroll
    for (int mi = 0; mi < 2; mi++)
        #pragma unroll
        for (int ni = 0; ni < 4; ni++) {
            float e0 = acc[mi][ni][0], e1 = acc[mi][ni][1];
            float e2 = acc[mi][ni][2], e3 = acc[mi][ni][3];
            if (rnd) {
                e0 = __uint_as_float(cvt_tf32(e0));
                e1 = __uint_as_float(cvt_tf32(e1));
                e2 = __uint_as_float(cvt_tf32(e2));
                e3 = __uint_as_float(cvt_tf32(e3));
            }
            int row = m0 + wm * 32 + mi * 16 + gr;
            int col = n0 + wn * 32 + ni * 8 + 2 * qq;
            *reinterpret_cast<float2*>(C + (size_t)row * N + col) =
                make_float2(e0, e1);
            *reinterpret_cast<float2*>(C + (size_t)(row + 8) * N + col) =
                make_float2(e2, e3);
        }
}

// ---------------------------------------------------------------------------
// kv0: out[b][h][n][d] = c[b][n][h*64+d]; also writes RNA-rounded copy of c
// ---------------------------------------------------------------------------
__global__ __launch_bounds__(256) void kv0_kernel(
    const float* __restrict__ c, float4* __restrict__ out,
    float4* __restrict__ cr)
{
    int i = blockIdx.x * 256 + threadIdx.x;
    int d4 = i & 15;
    int n  = (i >> 4) & (kNC - 1);
    int h  = (i >> 16) & (kH - 1);
    int b  = i >> 20;
    size_t sidx = (size_t)(b * kNC + n) * (kD / 4) + h * 16 + d4;
    float4 v = reinterpret_cast<const float4*>(c)[sidx];
    out[i] = v;
    uint4 r;
    r.x = cvt_tf32(v.x); r.y = cvt_tf32(v.y);
    r.z = cvt_tf32(v.z); r.w = cvt_tf32(v.w);
    *reinterpret_cast<uint4*>(&cr[sidx]) = r;
}

// ---------------------------------------------------------------------------
// mask bit-pack prepass
// ---------------------------------------------------------------------------
__global__ __launch_bounds__(256) void maskbits_kernel(
    const int* __restrict__ m, uint32_t* __restrict__ bits)
{
    int i = blockIdx.x * 256 + threadIdx.x;
    uint32_t b = __ballot_sync(0xffffffffu, m[i] != 0);
    if ((threadIdx.x & 31) == 0) bits[i >> 5] = b;
}

// ---------------------------------------------------------------------------
// Flash attention, tf32 mma, split-KV x2. Block = 128 thr (4 warps),
// warp = 16 q rows x 64 keys/tile, 36 tiles per split.
// Inputs pre-rounded to tf32 (q by tgemm epilogue, ctx by kv0) -> no cvt here.
// smem: Qs/Ps [64][68] | K double [2][64][68] | V single [64][72]  (69 KB)
// Grid = B*H*8*2 = 512.
// ---------------------------------------------------------------------------
static constexpr int S_QS  = 0;
static constexpr int S_KS  = 64 * 68;
static constexpr int KBUF  = 64 * 68;
static constexpr int S_VS  = S_KS + 2 * KBUF;
static constexpr int S_TOT = S_VS + 64 * 72;          // 17664 floats
static constexpr int SMEM_ATTN_BYTES = S_TOT * 4;     // 70656

__global__ __launch_bounds__(128) void attn_kernel(
    const float* __restrict__ q_s, const float* __restrict__ ctx,
    const uint32_t* __restrict__ bm,
    float* __restrict__ pO, float2* __restrict__ pml)
{
    extern __shared__ float sm[];
    float* Qs = sm + S_QS;   // staging for Q, then Ps
    float* Ps = Qs;

    uint32_t sbase = (uint32_t)__cvta_generic_to_shared(sm);

    int tid  = threadIdx.x;
    int lane = tid & 31, w = tid >> 5;
    int gr = lane >> 2, q = lane & 3;
    int bi = blockIdx.x;
    int qt = bi & 7;
    int h  = (bi >> 3) & 15;
    int b  = (bi >> 7) & 1;
    int sp = bi >> 8;
    int q0 = qt * 64;
    int tbase = sp * kNTS;

    auto tsrc = [&](int g) -> const float* {
        return (g < 8)
            ? q_s + ((size_t)(b * kNX + g * 64)) * kD + h * kHD
            : ctx + ((size_t)(b * kNC + (g - 8) * 64)) * kD + h * kHD;
    };
    auto issue_k = [&](int g, int buf) {
        const float* src = tsrc(g);
        uint32_t kd = sbase + (uint32_t)(S_KS + buf * KBUF) * 4;
        #pragma unroll
        for (int j = 0; j < 8; j++) {
            int idx = tid + 128 * j;
            int r = idx >> 4, c4 = idx & 15;
            cpa16(kd + (uint32_t)(r * 68 + c4 * 4) * 4,
                  src + (size_t)r * kD + c4 * 4);
        }
    };
    auto issue_v = [&](int g) {
        const float* src = tsrc(g);
        uint32_t vd = sbase + (uint32_t)S_VS * 4;
        #pragma unroll
        for (int j = 0; j < 8; j++) {
            int idx = tid + 128 * j;
            int r = idx >> 4, c4 = idx & 15;
            cpa16(vd + (uint32_t)(r * 72 + c4 * 4) * 4,
                  src + (size_t)r * kD + c4 * 4);
        }
    };

    // prefetch first tile (K buf 0 + V)
    issue_k(tbase, 0);
    issue_v(tbase);
    cp_commit();

    // ---- stage Q tile (values already tf32; *0.125 is exact) ----
    {
        const float* src = q_s + ((size_t)(b * kNX + q0)) * kD + h * kHD;
        #pragma unroll
        for (int j = 0; j < 8; j++) {
            int idx = tid + 128 * j;
            int r = idx >> 4, c4 = idx & 15;
            float4 v = *reinterpret_cast<const float4*>(src + (size_t)r * kD + c4 * 4);
            v.x *= ATT_SCALE; v.y *= ATT_SCALE;
            v.z *= ATT_SCALE; v.w *= ATT_SCALE;
            *reinterpret_cast<float4*>(&Qs[r * 68 + c4 * 4]) = v;
        }
    }
    __syncthreads();

    // ---- extract Q A-fragments ----
    uint32_t qa[8][4];
    int qr0 = (w * 16 + gr) * 68;
    int qr1 = qr0 + 8 * 68;
    #pragma unroll
    for (int s = 0; s < 8; s++) {
        qa[s][0] = __float_as_uint(Qs[qr0 + s * 8 + q]);
        qa[s][1] = __float_as_uint(Qs[qr1 + s * 8 + q]);
        qa[s][2] = __float_as_uint(Qs[qr0 + s * 8 + q + 4]);
        qa[s][3] = __float_as_uint(Qs[qr1 + s * 8 + q + 4]);
    }
    __syncthreads();   // Qs now free -> Ps

    float o[8][4];
    #pragma unroll
    for (int dt = 0; dt < 8; dt++)
        #pragma unroll
        for (int c = 0; c < 4; c++) o[dt][c] = 0.f;
    float mi0 = -1e30f, mi1 = -1e30f, li0 = 0.f, li1 = 0.f;

    const uint32_t* mrow0 = bm + ((size_t)(b * kNX + q0 + w * 16 + gr)) * (kNC / 32);
    const uint32_t* mrow1 = mrow0 + 8 * (kNC / 32);

    for (int t = 0; t < kNTS; t++) {
        int g = tbase + t;
        if (t + 1 < kNTS) {
            issue_k(g + 1, (t + 1) & 1);
            cp_commit();
        }

        bool masked = (g >= 8);
        uint2 mw0, mw1;
        if (masked) {
            mw0 = *reinterpret_cast<const uint2*>(mrow0 + (g - 8) * 2);
            mw1 = *reinterpret_cast<const uint2*>(mrow1 + (g - 8) * 2);
        }

        if (t + 1 < kNTS) cp_wait1(); else cp_wait0();
        __syncthreads();

        const float* Kc = sm + S_KS + (t & 1) * KBUF;
        const float* Vc = sm + S_VS;

        // ---- S = Q . K^T (ks-outer: 8 independent accumulator chains) ----
        float s[8][4];
        #pragma unroll
        for (int j = 0; j < 8; j++) {
            s[j][0] = 0.f; s[j][1] = 0.f; s[j][2] = 0.f; s[j][3] = 0.f;
        }
        const float* kb = Kc + gr * 68 + q;
        #pragma unroll
        for (int ks = 0; ks < 8; ks++) {
            #pragma unroll
            for (int j = 0; j < 8; j++) {
                const float* kj = kb + j * (8 * 68);
                uint32_t b0 = __float_as_uint(kj[ks * 8]);
                uint32_t b1 = __float_as_uint(kj[ks * 8 + 4]);
                mma_tf32(s[j], qa[ks], b0, b1);
            }
        }

        if (masked) {
            #pragma unroll
            for (int j = 0; j < 8; j++) {
                uint32_t w0 = (j < 4) ? mw0.x : mw0.y;
                uint32_t w1 = (j < 4) ? mw1.x : mw1.y;
                int bit = (8 * j + 2 * q) & 31;
                if (!((w0 >> bit) & 1u))       s[j][0] = -1e30f;
                if (!((w0 >> (bit + 1)) & 1u)) s[j][1] = -1e30f;
                if (!((w1 >> bit) & 1u))       s[j][2] = -1e30f;
                if (!((w1 >> (bit + 1)) & 1u)) s[j][3] = -1e30f;
            }
        }

        // ---- online softmax (clamped so an all-masked tile stays inert) ----
        float mx0 = -1e30f, mx1 = -1e30f;
        #pragma unroll
        for (int j = 0; j < 8; j++) {
            mx0 = fmaxf(mx0, fmaxf(s[j][0], s[j][1]));
            mx1 = fmaxf(mx1, fmaxf(s[j][2], s[j][3]));
        }
        mx0 = fmaxf(mx0, __shfl_xor_sync(0xffffffffu, mx0, 1));
        mx0 = fmaxf(mx0, __shfl_xor_sync(0xffffffffu, mx0, 2));
        mx1 = fmaxf(mx1, __shfl_xor_sync(0xffffffffu, mx1, 1));
        mx1 = fmaxf(mx1, __shfl_xor_sync(0xffffffffu, mx1, 2));
        float mn0 = fmaxf(fmaxf(mi0, mx0), -1e29f);
        float mn1 = fmaxf(fmaxf(mi1, mx1), -1e29f);
        float corr0 = __expf(mi0 - mn0), corr1 = __expf(mi1 - mn1);
        mi0 = mn0; mi1 = mn1;

        float sum0 = 0.f, sum1 = 0.f;
        #pragma unroll
        for (int j = 0; j < 8; j++) {
            float p0 = __expf(s[j][0] - mn0);
            float p1 = __expf(s[j][1] - mn0);
            float p2 = __expf(s[j][2] - mn1);
            float p3 = __expf(s[j][3] - mn1);
            sum0 += p0 + p1;
            sum1 += p2 + p3;
            float2 st0, st1;
            st0.x = __uint_as_float(cvt_tf32(p0));
            st0.y = __uint_as_float(cvt_tf32(p1));
            st1.x = __uint_as_float(cvt_tf32(p2));
            st1.y = __uint_as_float(cvt_tf32(p3));
            *reinterpret_cast<float2*>(&Ps[qr0 + 8 * j + 2 * q]) = st0;
            *reinterpret_cast<float2*>(&Ps[qr1 + 8 * j + 2 * q]) = st1;
        }
        sum0 += __shfl_xor_sync(0xffffffffu, sum0, 1);
        sum0 += __shfl_xor_sync(0xffffffffu, sum0, 2);
        sum1 += __shfl_xor_sync(0xffffffffu, sum1, 1);
        sum1 += __shfl_xor_sync(0xffffffffu, sum1, 2);
        li0 = li0 * corr0 + sum0;
        li1 = li1 * corr1 + sum1;
        #pragma unroll
        for (int dt = 0; dt < 8; dt++) {
            o[dt][0] *= corr0; o[dt][1] *= corr0;
            o[dt][2] *= corr1; o[dt][3] *= corr1;
        }
        __syncwarp();   // Ps is per-warp private

        // ---- O += P . V ----
        const float* vb = Vc + q * 72 + gr;
        #pragma unroll
        for (int ks = 0; ks < 8; ks++) {
            uint32_t pa[4];
            pa[0] = __float_as_uint(Ps[qr0 + ks * 8 + q]);
            pa[1] = __float_as_uint(Ps[qr1 + ks * 8 + q]);
            pa[2] = __float_as_uint(Ps[qr0 + ks * 8 + q + 4]);
            pa[3] = __float_as_uint(Ps[qr1 + ks * 8 + q + 4]);
            const float* vk = vb + ks * (8 * 72);
            #pragma unroll
            for (int dt = 0; dt < 8; dt++) {
                uint32_t b0 = __float_as_uint(vk[dt * 8]);
                uint32_t b1 = __float_as_uint(vk[4 * 72 + dt * 8]);
                mma_tf32(o[dt], pa, b0, b1);
            }
        }
        __syncthreads();   // V consumed; safe to refill next iteration

        if (t + 1 < kNTS) {
            issue_v(g + 1);
            cp_commit();
        }
    }

    // ---- write split partials (unnormalized O + (m, l)) ----
    int row0 = q0 + w * 16 + gr;
    float* base = pO + (size_t)sp * kPO_N;
    float* d0 = base + ((size_t)(b * kNX + row0)) * kD + h * kHD + 2 * q;
    float* d1 = d0 + 8 * kD;
    #pragma unroll
    for (int dt = 0; dt < 8; dt++) {
        *reinterpret_cast<float2*>(d0 + dt * 8) = make_float2(o[dt][0], o[dt][1]);
        *reinterpret_cast<float2*>(d1 + dt * 8) = make_float2(o[dt][2], o[dt][3]);
    }
    if (q == 0) {
        float2* mlb = pml + (size_t)sp * kML_N;
        mlb[(b * kNX + row0) * kH + h]     = make_float2(mi0, li0);
        mlb[(b * kNX + row0 + 8) * kH + h] = make_float2(mi1, li1);
    }
}

// ---------------------------------------------------------------------------
// split combine: a = (e0*O0 + e1*O1) / (e0*l0 + e1*l1)
// ---------------------------------------------------------------------------
__global__ __launch_bounds__(256) void combine_kernel(
    const float4* __restrict__ pO, const float2* __restrict__ pml,
    float4* __restrict__ a)
{
    int i = blockIdx.x * 256 + threadIdx.x;     // < kB*kNX*kD/4 = 524288
    int h   = (i >> 4) & 15;
    int row = i >> 8;                            // b*kNX + row
    float2 ml0 = pml[row * kH + h];
    float2 ml1 = pml[kML_N + row * kH + h];
    float mm = fmaxf(ml0.x, ml1.x);
    float e0 = __expf(ml0.x - mm);
    float e1 = __expf(ml1.x - mm);
    float inv = 1.f / (e0 * ml0.y + e1 * ml1.y);
    float4 a0 = pO[i];
    float4 a1 = pO[kPO_N / 4 + i];
    float4 r;
    r.x = (a0.x * e0 + a1.x * e1) * inv;
    r.y = (a0.y * e0 + a1.y * e1) * inv;
    r.z = (a0.z * e0 + a1.z * e1) * inv;
    r.w = (a0.w * e0 + a1.w * e1) * inv;
    a[i] = r;
}

// ---------------------------------------------------------------------------
extern "C" void kernel_launch(void* const* d_in, const int* in_sizes, int n_in,
                              void* d_out, int out_size)
{
    (void)in_sizes; (void)n_in; (void)out_size;
    const float* x    = (const float*)d_in[0];
    const float* c    = (const float*)d_in[1];
    const int*   mask = (const int*)  d_in[2];
    const float* lnw  = (const float*)d_in[3];
    const float* lnb  = (const float*)d_in[4];
    const float* Wq   = (const float*)d_in[5];
    const float* Wo   = (const float*)d_in[6];

    float* o_out  = (float*)d_out;
    float* kv_out = o_out + (size_t)kB * kNX * kD;

    void *p_xn, *p_q, *p_a, *p_mb, *p_cr, *p_pO, *p_ml;
    cudaGetSymbolAddress(&p_xn, g_xn);
    cudaGetSymbolAddress(&p_q,  g_q);
    cudaGetSymbolAddress(&p_a,  g_a);
    cudaGetSymbolAddress(&p_mb, g_mbits);
    cudaGetSymbolAddress(&p_cr, g_cr);
    cudaGetSymbolAddress(&p_pO, g_pO);
    cudaGetSymbolAddress(&p_ml, g_ml);
    float* xn = (float*)p_xn;
    float* q  = (float*)p_q;
    float* a  = (float*)p_a;
    uint32_t* mb = (uint32_t*)p_mb;
    float* cr = (float*)p_cr;
    float* pO = (float*)p_pO;
    float2* ml = (float2*)p_ml;

    cudaFuncSetAttribute(attn_kernel,
                         cudaFuncAttributeMaxDynamicSharedMemorySize,
                         SMEM_ATTN_BYTES);
    cudaFuncSetAttribute(tgemm_kernel,
                         cudaFuncAttributeMaxDynamicSharedMemorySize,
                         TG_SMEM_BYTES);

    const int M = kB * kNX;   // 1024

    // 1) mask bit-pack (independent)
    maskbits_kernel<<<(kB * kNX * kNC) / 256, 256>>>(mask, mb);
    // 2) LayerNorm
    ln_kernel<<<M, 256>>>(x, lnw, lnb, xn);
    // 3) q = xn @ Wq  (3xTF32; epilogue RNA-rounds q for attention)
    tgemm_kernel<<<dim3(kD / 64, M / 128), 256, TG_SMEM_BYTES>>>(
        xn, Wq, q, M, kD, kD, 1);
    // 4) kv0 output + rounded ctx copy
    kv0_kernel<<<(kB * kH * kNC * kHD / 4) / 256, 256>>>(
        c, (float4*)kv_out, (float4*)cr);
    // 5) attention (tf32, split-KV x2)
    attn_kernel<<<kB * kH * (kNX / 64) * kSplits, 128, SMEM_ATTN_BYTES>>>(
        q, cr, mb, pO, ml);
    // 6) combine splits -> a
    combine_kernel<<<(kB * kNX * kD / 4) / 256, 256>>>(
        (const float4*)pO, (const float2*)ml, (float4*)a);
    // 7) o = a @ Wo  (exact fp32 output)
    tgemm_kernel<<<dim3(kD / 64, M / 128), 256, TG_SMEM_BYTES>>>(
        a, Wo, o_out, M, kD, kD, 0);
}

// round 17
// speedup vs baseline: 1.1022x; 1.1022x over previous
#include <cuda_runtime.h>
#include <math.h>
#include <stdint.h>

static constexpr int kB  = 2;
static constexpr int kNX = 512;
static constexpr int kNC = 4096;
static constexpr int kD  = 1024;
static constexpr int kH  = 16;
static constexpr int kHD = 64;
#define ATT_SCALE 0.125f   // HD^-0.5

static constexpr int kNT     = kNX / 64 + kNC / 64;  // 72 key tiles
static constexpr int kSplits = 2;
static constexpr int kNTS    = kNT / kSplits;        // 36 tiles per split
static constexpr int kPO_N   = kB * kNX * kD;        // floats per split partial
static constexpr int kML_N   = kB * kNX * kH;        // float2 per split

// Scratch (allocation-free rule: __device__ globals)
__device__ float g_xn[kB * kNX * kD];
__device__ float g_q [kB * kNX * kD];
__device__ float g_a [kB * kNX * kD];
__device__ float g_cr[kB * kNC * kD];                // RNA-rounded ctx
__device__ float g_pO[kSplits * kPO_N];              // split partial O
__device__ float2 g_ml[kSplits * kML_N];             // split (m, l)
__device__ uint32_t g_mbits[(size_t)kB * kNX * kNC / 32];

// ---------------------------------------------------------------------------
// tf32 mma helpers
// ---------------------------------------------------------------------------
__device__ __forceinline__ uint32_t cvt_tf32(float x) {
    uint32_t u;
    asm("cvt.rna.tf32.f32 %0, %1;" : "=r"(u) : "f"(x));
    return u;
}
__device__ __forceinline__ void mma_tf32(float c[4], const uint32_t a[4],
                                         uint32_t b0, uint32_t b1) {
    asm volatile(
        "mma.sync.aligned.m16n8k8.row.col.f32.tf32.tf32.f32 "
        "{%0,%1,%2,%3}, {%4,%5,%6,%7}, {%8,%9}, {%0,%1,%2,%3};"
        : "+f"(c[0]), "+f"(c[1]), "+f"(c[2]), "+f"(c[3])
        : "r"(a[0]), "r"(a[1]), "r"(a[2]), "r"(a[3]), "r"(b0), "r"(b1));
}

// ---------------------------------------------------------------------------
// cp.async helpers
// ---------------------------------------------------------------------------
__device__ __forceinline__ void cpa16(uint32_t dst, const void* src) {
    asm volatile("cp.async.cg.shared.global [%0], [%1], 16;"
                 :: "r"(dst), "l"(src));
}
__device__ __forceinline__ void cp_commit() {
    asm volatile("cp.async.commit_group;" ::: "memory");
}
__device__ __forceinline__ void cp_wait1() {
    asm volatile("cp.async.wait_group 1;" ::: "memory");
}
__device__ __forceinline__ void cp_wait0() {
    asm volatile("cp.async.wait_group 0;" ::: "memory");
}

// ---------------------------------------------------------------------------
// LayerNorm
// ---------------------------------------------------------------------------
__global__ __launch_bounds__(256) void ln_kernel(
    const float* __restrict__ x, const float* __restrict__ w,
    const float* __restrict__ bb, float* __restrict__ out)
{
    int row = blockIdx.x;
    int tid = threadIdx.x;
    float4 v = reinterpret_cast<const float4*>(x + (size_t)row * kD)[tid];
    float s  = v.x + v.y + v.z + v.w;
    float sq = v.x*v.x + v.y*v.y + v.z*v.z + v.w*v.w;
    #pragma unroll
    for (int o = 16; o; o >>= 1) {
        s  += __shfl_xor_sync(0xffffffffu, s,  o);
        sq += __shfl_xor_sync(0xffffffffu, sq, o);
    }
    __shared__ float ss[8], ssq[8];
    int wid = tid >> 5, lid = tid & 31;
    if (lid == 0) { ss[wid] = s; ssq[wid] = sq; }
    __syncthreads();
    if (wid == 0) {
        s  = (lid < 8) ? ss[lid]  : 0.f;
        sq = (lid < 8) ? ssq[lid] : 0.f;
        #pragma unroll
        for (int o = 4; o; o >>= 1) {
            s  += __shfl_xor_sync(0xffffffffu, s,  o);
            sq += __shfl_xor_sync(0xffffffffu, sq, o);
        }
        if (lid == 0) { ss[0] = s; ssq[0] = sq; }
    }
    __syncthreads();
    float mu   = ss[0] * (1.f / kD);
    float var  = ssq[0] * (1.f / kD) - mu * mu;
    float rstd = rsqrtf(var + 1e-5f);
    float4 w4 = reinterpret_cast<const float4*>(w)[tid];
    float4 b4 = reinterpret_cast<const float4*>(bb)[tid];
    float4 o4;
    o4.x = (v.x - mu) * rstd * w4.x + b4.x;
    o4.y = (v.y - mu) * rstd * w4.y + b4.y;
    o4.z = (v.z - mu) * rstd * w4.z + b4.z;
    o4.w = (v.w - mu) * rstd * w4.w + b4.w;
    reinterpret_cast<float4*>(out + (size_t)row * kD)[tid] = o4;
}

// ---------------------------------------------------------------------------
// 3xTF32 split GEMM: C = A @ B, fp32-accurate. rnd!=0 -> RNA-round outputs.
// ---------------------------------------------------------------------------
static constexpr int TG_AH = 0;
static constexpr int TG_AL = 4608;
static constexpr int TG_BH = 9216;
static constexpr int TG_BL = 11520;
static constexpr int TG_TOT = 13824;
static constexpr int TG_SMEM_BYTES = TG_TOT * 4;

__global__ __launch_bounds__(256) void tgemm_kernel(
    const float* __restrict__ A, const float* __restrict__ Bm,
    float* __restrict__ C, int M, int N, int K, int rnd)
{
    extern __shared__ float ts[];
    float* Ah = ts + TG_AH;
    float* Al = ts + TG_AL;
    float* Bh = ts + TG_BH;
    float* Bl = ts + TG_BL;

    int tid  = threadIdx.x;
    int lane = tid & 31, wid = tid >> 5;
    int gr = lane >> 2, qq = lane & 3;
    int wm = wid >> 1, wn = wid & 1;
    int m0 = blockIdx.y * 128, n0 = blockIdx.x * 64;

    float acc[2][4][4];
    #pragma unroll
    for (int mi = 0; mi < 2; mi++)
        #pragma unroll
        for (int ni = 0; ni < 4; ni++)
            #pragma unroll
            for (int e = 0; e < 4; e++) acc[mi][ni][e] = 0.f;

    for (int k0 = 0; k0 < K; k0 += 32) {
        __syncthreads();
        #pragma unroll
        for (int j = 0; j < 4; j++) {
            int f = tid + 256 * j;
            int m = f >> 3, c4 = f & 7;
            float4 v = *reinterpret_cast<const float4*>(
                A + (size_t)(m0 + m) * K + k0 + c4 * 4);
            uint4 hb, lb;
            hb.x = cvt_tf32(v.x); lb.x = cvt_tf32(v.x - __uint_as_float(hb.x));
            hb.y = cvt_tf32(v.y); lb.y = cvt_tf32(v.y - __uint_as_float(hb.y));
            hb.z = cvt_tf32(v.z); lb.z = cvt_tf32(v.z - __uint_as_float(hb.z));
            hb.w = cvt_tf32(v.w); lb.w = cvt_tf32(v.w - __uint_as_float(hb.w));
            *reinterpret_cast<uint4*>(&Ah[m * 36 + c4 * 4]) = hb;
            *reinterpret_cast<uint4*>(&Al[m * 36 + c4 * 4]) = lb;
        }
        #pragma unroll
        for (int j = 0; j < 2; j++) {
            int f = tid + 256 * j;
            int kk = f >> 4, c4 = f & 15;
            float4 v = *reinterpret_cast<const float4*>(
                Bm + (size_t)(k0 + kk) * N + n0 + c4 * 4);
            uint4 hb, lb;
            hb.x = cvt_tf32(v.x); lb.x = cvt_tf32(v.x - __uint_as_float(hb.x));
            hb.y = cvt_tf32(v.y); lb.y = cvt_tf32(v.y - __uint_as_float(hb.y));
            hb.z = cvt_tf32(v.z); lb.z = cvt_tf32(v.z - __uint_as_float(hb.z));
            hb.w = cvt_tf32(v.w); lb.w = cvt_tf32(v.w - __uint_as_float(hb.w));
            *reinterpret_cast<uint4*>(&Bh[kk * 72 + c4 * 4]) = hb;
            *reinterpret_cast<uint4*>(&Bl[kk * 72 + c4 * 4]) = lb;
        }
        __syncthreads();

        #pragma unroll
        for (int ks = 0; ks < 4; ks++) {
            int ko = ks * 8 + qq;
            uint32_t ah[2][4], al[2][4];
            #pragma unroll
            for (int mi = 0; mi < 2; mi++) {
                int row = (wm * 32 + mi * 16 + gr) * 36;
                ah[mi][0] = __float_as_uint(Ah[row + ko]);
                ah[mi][1] = __float_as_uint(Ah[row + 8 * 36 + ko]);
                ah[mi][2] = __float_as_uint(Ah[row + ko + 4]);
                ah[mi][3] = __float_as_uint(Ah[row + 8 * 36 + ko + 4]);
                al[mi][0] = __float_as_uint(Al[row + ko]);
                al[mi][1] = __float_as_uint(Al[row + 8 * 36 + ko]);
                al[mi][2] = __float_as_uint(Al[row + ko + 4]);
                al[mi][3] = __float_as_uint(Al[row + 8 * 36 + ko + 4]);
            }
            #pragma unroll
            for (int ni = 0; ni < 4; ni++) {
                int n = wn * 32 + ni * 8 + gr;
                uint32_t bh0 = __float_as_uint(Bh[ko * 72 + n]);
                uint32_t bh1 = __float_as_uint(Bh[(ko + 4) * 72 + n]);
                uint32_t bl0 = __float_as_uint(Bl[ko * 72 + n]);
                uint32_t bl1 = __float_as_uint(Bl[(ko + 4) * 72 + n]);
                #pragma unroll
                for (int mi = 0; mi < 2; mi++) {
                    mma_tf32(acc[mi][ni], ah[mi], bh0, bh1);
                    mma_tf32(acc[mi][ni], ah[mi], bl0, bl1);
                    mma_tf32(acc[mi][ni], al[mi], bh0, bh1);
                }
            }
        }
    }
    #pragma unroll
    for (int mi = 0; mi < 2; mi++)
        #pragma unroll
        for (int ni = 0; ni < 4; ni++) {
            float e0 = acc[mi][ni][0], e1 = acc[mi][ni][1];
            float e2 = acc[mi][ni][2], e3 = acc[mi][ni][3];
            if (rnd) {
                e0 = __uint_as_float(cvt_tf32(e0));
                e1 = __uint_as_float(cvt_tf32(e1));
                e2 = __uint_as_float(cvt_tf32(e2));
                e3 = __uint_as_float(cvt_tf32(e3));
            }
            int row = m0 + wm * 32 + mi * 16 + gr;
            int col = n0 + wn * 32 + ni * 8 + 2 * qq;
            *reinterpret_cast<float2*>(C + (size_t)row * N + col) =
                make_float2(e0, e1);
            *reinterpret_cast<float2*>(C + (size_t)(row + 8) * N + col) =
                make_float2(e2, e3);
        }
}

// ---------------------------------------------------------------------------
// kv0: out[b][h][n][d] = c[b][n][h*64+d]; also writes RNA-rounded copy of c
// ---------------------------------------------------------------------------
__global__ __launch_bounds__(256) void kv0_kernel(
    const float* __restrict__ c, float4* __restrict__ out,
    float4* __restrict__ cr)
{
    int i = blockIdx.x * 256 + threadIdx.x;
    int d4 = i & 15;
    int n  = (i >> 4) & (kNC - 1);
    int h  = (i >> 16) & (kH - 1);
    int b  = i >> 20;
    size_t sidx = (size_t)(b * kNC + n) * (kD / 4) + h * 16 + d4;
    float4 v = reinterpret_cast<const float4*>(c)[sidx];
    out[i] = v;
    uint4 r;
    r.x = cvt_tf32(v.x); r.y = cvt_tf32(v.y);
    r.z = cvt_tf32(v.z); r.w = cvt_tf32(v.w);
    *reinterpret_cast<uint4*>(&cr[sidx]) = r;
}

// ---------------------------------------------------------------------------
// mask bit-pack prepass
// ---------------------------------------------------------------------------
__global__ __launch_bounds__(256) void maskbits_kernel(
    const int* __restrict__ m, uint32_t* __restrict__ bits)
{
    int i = blockIdx.x * 256 + threadIdx.x;
    uint32_t b = __ballot_sync(0xffffffffu, m[i] != 0);
    if ((threadIdx.x & 31) == 0) bits[i >> 5] = b;
}

// ---------------------------------------------------------------------------
// Flash attention, tf32 mma, split-KV x2, 2 m-tiles per warp.
// Block = 128 thr (4 warps); warp = 32 q rows x 64 keys; block = 128 q rows.
// K/V B-fragments amortized over 2 m-tiles -> LDS/MMA drops 2.37 -> 1.37.
// smem: Qs/Ps [128][68] | K double [2][64][68] | V [64][72]
// Grid = B*H*4*splits = 256.
// ---------------------------------------------------------------------------
static constexpr int S_QS  = 0;
static constexpr int QSZ   = 128 * 68;                // 8704
static constexpr int S_KS  = QSZ;
static constexpr int KBUF  = 64 * 68;
static constexpr int S_VS  = S_KS + 2 * KBUF;         // 17408
static constexpr int S_TOT = S_VS + 64 * 72;          // 22016 floats
static constexpr int SMEM_ATTN_BYTES = S_TOT * 4;     // 88064

__global__ __launch_bounds__(128, 2) void attn_kernel(
    const float* __restrict__ q_s, const float* __restrict__ ctx,
    const uint32_t* __restrict__ bm,
    float* __restrict__ pO, float2* __restrict__ pml)
{
    extern __shared__ float sm[];
    float* Qs = sm + S_QS;   // staging for Q, then Ps
    float* Ps = Qs;

    uint32_t sbase = (uint32_t)__cvta_generic_to_shared(sm);

    int tid  = threadIdx.x;
    int lane = tid & 31, w = tid >> 5;
    int gr = lane >> 2, q = lane & 3;
    int bi = blockIdx.x;
    int qt = bi & 3;
    int h  = (bi >> 2) & 15;
    int b  = (bi >> 6) & 1;
    int sp = bi >> 7;
    int q0 = qt * 128;
    int wb = w * 32;               // warp's base q row within block
    int tbase = sp * kNTS;

    auto tsrc = [&](int g) -> const float* {
        return (g < 8)
            ? q_s + ((size_t)(b * kNX + g * 64)) * kD + h * kHD
            : ctx + ((size_t)(b * kNC + (g - 8) * 64)) * kD + h * kHD;
    };
    auto issue_k = [&](int g, int buf) {
        const float* src = tsrc(g);
        uint32_t kd = sbase + (uint32_t)(S_KS + buf * KBUF) * 4;
        #pragma unroll
        for (int j = 0; j < 8; j++) {
            int idx = tid + 128 * j;
            int r = idx >> 4, c4 = idx & 15;
            cpa16(kd + (uint32_t)(r * 68 + c4 * 4) * 4,
                  src + (size_t)r * kD + c4 * 4);
        }
    };
    auto issue_v = [&](int g) {
        const float* src = tsrc(g);
        uint32_t vd = sbase + (uint32_t)S_VS * 4;
        #pragma unroll
        for (int j = 0; j < 8; j++) {
            int idx = tid + 128 * j;
            int r = idx >> 4, c4 = idx & 15;
            cpa16(vd + (uint32_t)(r * 72 + c4 * 4) * 4,
                  src + (size_t)r * kD + c4 * 4);
        }
    };

    // prefetch first tile (K buf 0 + V)
    issue_k(tbase, 0);
    issue_v(tbase);
    cp_commit();

    // ---- stage Q tile: 128 rows (values already tf32; *0.125 exact) ----
    {
        const float* src = q_s + ((size_t)(b * kNX + q0)) * kD + h * kHD;
        #pragma unroll
        for (int j = 0; j < 16; j++) {
            int idx = tid + 128 * j;
            int r = idx >> 4, c4 = idx & 15;
            float4 v = *reinterpret_cast<const float4*>(src + (size_t)r * kD + c4 * 4);
            v.x *= ATT_SCALE; v.y *= ATT_SCALE;
            v.z *= ATT_SCALE; v.w *= ATT_SCALE;
            *reinterpret_cast<float4*>(&Qs[r * 68 + c4 * 4]) = v;
        }
    }
    __syncthreads();

    // ---- extract Q A-fragments: 2 m-tiles x 8 k-steps ----
    uint32_t qa[2][8][4];
    int qr[2];
    qr[0] = (wb + gr) * 68;
    qr[1] = (wb + 16 + gr) * 68;
    #pragma unroll
    for (int mi = 0; mi < 2; mi++)
        #pragma unroll
        for (int s = 0; s < 8; s++) {
            qa[mi][s][0] = __float_as_uint(Qs[qr[mi] + s * 8 + q]);
            qa[mi][s][1] = __float_as_uint(Qs[qr[mi] + 8 * 68 + s * 8 + q]);
            qa[mi][s][2] = __float_as_uint(Qs[qr[mi] + s * 8 + q + 4]);
            qa[mi][s][3] = __float_as_uint(Qs[qr[mi] + 8 * 68 + s * 8 + q + 4]);
        }
    __syncthreads();   // Qs now free -> Ps

    float o[2][8][4];
    #pragma unroll
    for (int mi = 0; mi < 2; mi++)
        #pragma unroll
        for (int dt = 0; dt < 8; dt++)
            #pragma unroll
            for (int e = 0; e < 4; e++) o[mi][dt][e] = 0.f;
    // softmax state: index rg = mi*2 + (0: rows gr, 1: rows gr+8)
    float mi_s[4] = {-1e30f, -1e30f, -1e30f, -1e30f};
    float li_s[4] = {0.f, 0.f, 0.f, 0.f};

    const uint32_t* mrow[4];
    mrow[0] = bm + ((size_t)(b * kNX + q0 + wb + gr)) * (kNC / 32);
    mrow[1] = mrow[0] + 8  * (kNC / 32);
    mrow[2] = mrow[0] + 16 * (kNC / 32);
    mrow[3] = mrow[0] + 24 * (kNC / 32);

    for (int t = 0; t < kNTS; t++) {
        int g = tbase + t;
        if (t + 1 < kNTS) {
            issue_k(g + 1, (t + 1) & 1);
            cp_commit();
        }

        bool masked = (g >= 8);
        uint2 mw[4];
        if (masked) {
            #pragma unroll
            for (int r = 0; r < 4; r++)
                mw[r] = *reinterpret_cast<const uint2*>(mrow[r] + (g - 8) * 2);
        }

        if (t + 1 < kNTS) cp_wait1(); else cp_wait0();
        __syncthreads();

        const float* Kc = sm + S_KS + (t & 1) * KBUF;
        const float* Vc = sm + S_VS;

        // ---- S = Q . K^T : B-frags shared across both m-tiles ----
        float s[2][8][4];
        #pragma unroll
        for (int mi2 = 0; mi2 < 2; mi2++)
            #pragma unroll
            for (int j = 0; j < 8; j++) {
                s[mi2][j][0] = 0.f; s[mi2][j][1] = 0.f;
                s[mi2][j][2] = 0.f; s[mi2][j][3] = 0.f;
            }
        const float* kb = Kc + gr * 68 + q;
        #pragma unroll
        for (int ks = 0; ks < 8; ks++) {
            #pragma unroll
            for (int j = 0; j < 8; j++) {
                const float* kj = kb + j * (8 * 68);
                uint32_t b0 = __float_as_uint(kj[ks * 8]);
                uint32_t b1 = __float_as_uint(kj[ks * 8 + 4]);
                mma_tf32(s[0][j], qa[0][ks], b0, b1);
                mma_tf32(s[1][j], qa[1][ks], b0, b1);
            }
        }

        if (masked) {
            #pragma unroll
            for (int mi2 = 0; mi2 < 2; mi2++)
                #pragma unroll
                for (int j = 0; j < 8; j++) {
                    uint32_t w0 = (j < 4) ? mw[mi2 * 2].x     : mw[mi2 * 2].y;
                    uint32_t w1 = (j < 4) ? mw[mi2 * 2 + 1].x : mw[mi2 * 2 + 1].y;
                    int bit = (8 * j + 2 * q) & 31;
                    if (!((w0 >> bit) & 1u))       s[mi2][j][0] = -1e30f;
                    if (!((w0 >> (bit + 1)) & 1u)) s[mi2][j][1] = -1e30f;
                    if (!((w1 >> bit) & 1u))       s[mi2][j][2] = -1e30f;
                    if (!((w1 >> (bit + 1)) & 1u)) s[mi2][j][3] = -1e30f;
                }
        }

        // ---- online softmax, 4 row-groups ----
        #pragma unroll
        for (int mi2 = 0; mi2 < 2; mi2++) {
            float mx0 = -1e30f, mx1 = -1e30f;
            #pragma unroll
            for (int j = 0; j < 8; j++) {
                mx0 = fmaxf(mx0, fmaxf(s[mi2][j][0], s[mi2][j][1]));
                mx1 = fmaxf(mx1, fmaxf(s[mi2][j][2], s[mi2][j][3]));
            }
            mx0 = fmaxf(mx0, __shfl_xor_sync(0xffffffffu, mx0, 1));
            mx0 = fmaxf(mx0, __shfl_xor_sync(0xffffffffu, mx0, 2));
            mx1 = fmaxf(mx1, __shfl_xor_sync(0xffffffffu, mx1, 1));
            mx1 = fmaxf(mx1, __shfl_xor_sync(0xffffffffu, mx1, 2));
            float mn0 = fmaxf(fmaxf(mi_s[mi2 * 2], mx0), -1e29f);
            float mn1 = fmaxf(fmaxf(mi_s[mi2 * 2 + 1], mx1), -1e29f);
            float corr0 = __expf(mi_s[mi2 * 2] - mn0);
            float corr1 = __expf(mi_s[mi2 * 2 + 1] - mn1);
            mi_s[mi2 * 2] = mn0; mi_s[mi2 * 2 + 1] = mn1;

            float sum0 = 0.f, sum1 = 0.f;
            #pragma unroll
            for (int j = 0; j < 8; j++) {
                float p0 = __expf(s[mi2][j][0] - mn0);
                float p1 = __expf(s[mi2][j][1] - mn0);
                float p2 = __expf(s[mi2][j][2] - mn1);
                float p3 = __expf(s[mi2][j][3] - mn1);
                sum0 += p0 + p1;
                sum1 += p2 + p3;
                float2 st0, st1;
                st0.x = __uint_as_float(cvt_tf32(p0));
                st0.y = __uint_as_float(cvt_tf32(p1));
                st1.x = __uint_as_float(cvt_tf32(p2));
                st1.y = __uint_as_float(cvt_tf32(p3));
                *reinterpret_cast<float2*>(&Ps[qr[mi2] + 8 * j + 2 * q]) = st0;
                *reinterpret_cast<float2*>(&Ps[qr[mi2] + 8 * 68 + 8 * j + 2 * q]) = st1;
            }
            sum0 += __shfl_xor_sync(0xffffffffu, sum0, 1);
            sum0 += __shfl_xor_sync(0xffffffffu, sum0, 2);
            sum1 += __shfl_xor_sync(0xffffffffu, sum1, 1);
            sum1 += __shfl_xor_sync(0xffffffffu, sum1, 2);
            li_s[mi2 * 2]     = li_s[mi2 * 2] * corr0 + sum0;
            li_s[mi2 * 2 + 1] = li_s[mi2 * 2 + 1] * corr1 + sum1;
            #pragma unroll
            for (int dt = 0; dt < 8; dt++) {
                o[mi2][dt][0] *= corr0; o[mi2][dt][1] *= corr0;
                o[mi2][dt][2] *= corr1; o[mi2][dt][3] *= corr1;
            }
        }
        __syncwarp();   // Ps region is per-warp private

        // ---- O += P . V : V B-frags shared across both m-tiles ----
        const float* vb = Vc + q * 72 + gr;
        #pragma unroll
        for (int ks = 0; ks < 8; ks++) {
            uint32_t pa[2][4];
            #pragma unroll
            for (int mi2 = 0; mi2 < 2; mi2++) {
                pa[mi2][0] = __float_as_uint(Ps[qr[mi2] + ks * 8 + q]);
                pa[mi2][1] = __float_as_uint(Ps[qr[mi2] + 8 * 68 + ks * 8 + q]);
                pa[mi2][2] = __float_as_uint(Ps[qr[mi2] + ks * 8 + q + 4]);
                pa[mi2][3] = __float_as_uint(Ps[qr[mi2] + 8 * 68 + ks * 8 + q + 4]);
            }
            const float* vk = vb + ks * (8 * 72);
            #pragma unroll
            for (int dt = 0; dt < 8; dt++) {
                uint32_t b0 = __float_as_uint(vk[dt * 8]);
                uint32_t b1 = __float_as_uint(vk[4 * 72 + dt * 8]);
                mma_tf32(o[0][dt], pa[0], b0, b1);
                mma_tf32(o[1][dt], pa[1], b0, b1);
            }
        }
        __syncthreads();   // V consumed; safe to refill next iteration

        if (t + 1 < kNTS) {
            issue_v(g + 1);
            cp_commit();
        }
    }

    // ---- write split partials (unnormalized O + (m, l)) ----
    float* base = pO + (size_t)sp * kPO_N;
    #pragma unroll
    for (int mi2 = 0; mi2 < 2; mi2++) {
        int row0 = q0 + wb + mi2 * 16 + gr;
        float* d0 = base + ((size_t)(b * kNX + row0)) * kD + h * kHD + 2 * q;
        float* d1 = d0 + 8 * kD;
        #pragma unroll
        for (int dt = 0; dt < 8; dt++) {
            *reinterpret_cast<float2*>(d0 + dt * 8) =
                make_float2(o[mi2][dt][0], o[mi2][dt][1]);
            *reinterpret_cast<float2*>(d1 + dt * 8) =
                make_float2(o[mi2][dt][2], o[mi2][dt][3]);
        }
    }
    if (q == 0) {
        float2* mlb = pml + (size_t)sp * kML_N;
        #pragma unroll
        for (int mi2 = 0; mi2 < 2; mi2++) {
            int row0 = q0 + wb + mi2 * 16 + gr;
            mlb[(b * kNX + row0) * kH + h] =
                make_float2(mi_s[mi2 * 2], li_s[mi2 * 2]);
            mlb[(b * kNX + row0 + 8) * kH + h] =
                make_float2(mi_s[mi2 * 2 + 1], li_s[mi2 * 2 + 1]);
        }
    }
}

// ---------------------------------------------------------------------------
// split combine: a = (e0*O0 + e1*O1) / (e0*l0 + e1*l1)
// ---------------------------------------------------------------------------
__global__ __launch_bounds__(256) void combine_kernel(
    const float4* __restrict__ pO, const float2* __restrict__ pml,
    float4* __restrict__ a)
{
    int i = blockIdx.x * 256 + threadIdx.x;     // < kB*kNX*kD/4 = 524288
    int h   = (i >> 4) & 15;
    int row = i >> 8;                            // b*kNX + row
    float2 ml0 = pml[row * kH + h];
    float2 ml1 = pml[kML_N + row * kH + h];
    float mm = fmaxf(ml0.x, ml1.x);
    float e0 = __expf(ml0.x - mm);
    float e1 = __expf(ml1.x - mm);
    float inv = 1.f / (e0 * ml0.y + e1 * ml1.y);
    float4 a0 = pO[i];
    float4 a1 = pO[kPO_N / 4 + i];
    float4 r;
    r.x = (a0.x * e0 + a1.x * e1) * inv;
    r.y = (a0.y * e0 + a1.y * e1) * inv;
    r.z = (a0.z * e0 + a1.z * e1) * inv;
    r.w = (a0.w * e0 + a1.w * e1) * inv;
    a[i] = r;
}

// ---------------------------------------------------------------------------
extern "C" void kernel_launch(void* const* d_in, const int* in_sizes, int n_in,
                              void* d_out, int out_size)
{
    (void)in_sizes; (void)n_in; (void)out_size;
    const float* x    = (const float*)d_in[0];
    const float* c    = (const float*)d_in[1];
    const int*   mask = (const int*)  d_in[2];
    const float* lnw  = (const float*)d_in[3];
    const float* lnb  = (const float*)d_in[4];
    const float* Wq   = (const float*)d_in[5];
    const float* Wo   = (const float*)d_in[6];

    float* o_out  = (float*)d_out;
    float* kv_out = o_out + (size_t)kB * kNX * kD;

    void *p_xn, *p_q, *p_a, *p_mb, *p_cr, *p_pO, *p_ml;
    cudaGetSymbolAddress(&p_xn, g_xn);
    cudaGetSymbolAddress(&p_q,  g_q);
    cudaGetSymbolAddress(&p_a,  g_a);
    cudaGetSymbolAddress(&p_mb, g_mbits);
    cudaGetSymbolAddress(&p_cr, g_cr);
    cudaGetSymbolAddress(&p_pO, g_pO);
    cudaGetSymbolAddress(&p_ml, g_ml);
    float* xn = (float*)p_xn;
    float* q  = (float*)p_q;
    float* a  = (float*)p_a;
    uint32_t* mb = (uint32_t*)p_mb;
    float* cr = (float*)p_cr;
    float* pO = (float*)p_pO;
    float2* ml = (float2*)p_ml;

    cudaFuncSetAttribute(attn_kernel,
                         cudaFuncAttributeMaxDynamicSharedMemorySize,
                         SMEM_ATTN_BYTES);
    cudaFuncSetAttribute(tgemm_kernel,
                         cudaFuncAttributeMaxDynamicSharedMemorySize,
                         TG_SMEM_BYTES);

    const int M = kB * kNX;   // 1024

    // 1) mask bit-pack (independent)
    maskbits_kernel<<<(kB * kNX * kNC) / 256, 256>>>(mask, mb);
    // 2) LayerNorm
    ln_kernel<<<M, 256>>>(x, lnw, lnb, xn);
    // 3) q = xn @ Wq  (3xTF32; epilogue RNA-rounds q for attention)
    tgemm_kernel<<<dim3(kD / 64, M / 128), 256, TG_SMEM_BYTES>>>(
        xn, Wq, q, M, kD, kD, 1);
    // 4) kv0 output + rounded ctx copy
    kv0_kernel<<<(kB * kH * kNC * kHD / 4) / 256, 256>>>(
        c, (float4*)kv_out, (float4*)cr);
    // 5) attention (tf32, split-KV x2, 2 m-tiles/warp)
    attn_kernel<<<kB * kH * (kNX / 128) * kSplits, 128, SMEM_ATTN_BYTES>>>(
        q, cr, mb, pO, ml);
    // 6) combine splits -> a
    combine_kernel<<<(kB * kNX * kD / 4) / 256, 256>>>(
        (const float4*)pO, (const float2*)ml, (float4*)a);
    // 7) o = a @ Wo  (exact fp32 output)
    tgemm_kernel<<<dim3(kD / 64, M / 128), 256, TG_SMEM_BYTES>>>(
        a, Wo, o_out, M, kD, kD, 0);
}